// round 6
// baseline (speedup 1.0000x reference)
#include <cuda_runtime.h>
#include <cstdint>

#define NTHREADS 256
#define ROWLEN   4096
#define KSEL     8
#define POOL_CAP 256

typedef unsigned long long u64;

// Monotone bijection float -> uint32 (order preserving)
__device__ __forceinline__ unsigned fflip(float f) {
    unsigned u = __float_as_uint(f);
    return (u & 0x80000000u) ? ~u : (u | 0x80000000u);
}
__device__ __forceinline__ float funflip(unsigned u) {
    return __uint_as_float((u & 0x80000000u) ? (u ^ 0x80000000u) : ~u);
}

__device__ __forceinline__ void push_cand(float x, float thr, int idx,
                                          int* s_cnt, u64* s_pool) {
    if (x >= thr) {
        int pos = atomicAdd(s_cnt, 1);
        if (pos < POOL_CAP)
            s_pool[pos] = ((u64)fflip(x) << 12) | (unsigned)(4095 - idx);
    }
}

__global__ __launch_bounds__(NTHREADS) void kmax_kernel(const float* __restrict__ in,
                                                        float* __restrict__ out) {
    __shared__ unsigned s_m[8];       // per-warp max (flipped), 8 warps
    __shared__ int s_cnt;
    __shared__ u64 s_pool[POOL_CAP];

    const int t = threadIdx.x;
    const int lane = t & 31;
    const int wid = t >> 5;
    const size_t row = blockIdx.x;
    const float4* rp = reinterpret_cast<const float4*>(in + row * (size_t)ROWLEN);

    // Front-batched streaming loads: 4x LDG.128 per thread.
    float4 v0 = __ldcs(rp + t);
    float4 v1 = __ldcs(rp + 256 + t);
    float4 v2 = __ldcs(rp + 512 + t);
    float4 v3 = __ldcs(rp + 768 + t);

    if (t == 0) s_cnt = 0;

    // Per-thread max over its 16 elements (15 FMNMX).
    float m01 = fmaxf(fmaxf(fmaxf(v0.x, v0.y), fmaxf(v0.z, v0.w)),
                      fmaxf(fmaxf(v1.x, v1.y), fmaxf(v1.z, v1.w)));
    float m23 = fmaxf(fmaxf(fmaxf(v2.x, v2.y), fmaxf(v2.z, v2.w)),
                      fmaxf(fmaxf(v3.x, v3.y), fmaxf(v3.z, v3.w)));
    const float gmax = fmaxf(m01, m23);
    const unsigned gx = fflip(gmax);

    // Warp max via hardware REDUX; publish per warp.
    unsigned m1 = __reduce_max_sync(0xffffffffu, gx);
    if (lane == 0) s_m[wid] = m1;
    __syncthreads();

    // Threshold T = MIN over the 8 warp maxes. Safety: each warp has >=1
    // element >= T -> >=8 elements >= T; any x < T is beaten by 8 warp maxes
    // -> every true top-8 element satisfies x >= T. Zero extra barrier phase.
    uint4 a = reinterpret_cast<const uint4*>(s_m)[0];
    uint4 b = reinterpret_cast<const uint4*>(s_m)[1];
    unsigned tf = min(min(min(a.x, a.y), min(a.z, a.w)),
                      min(min(b.x, b.y), min(b.z, b.w)));
    const float thr = funflip(tf);

    // Push candidate ELEMENTS (x >= thr). Typically ~9-25 per row; the vast
    // majority of threads skip this branch entirely.
    if (gmax >= thr) {
        int i0 = 4 * t;
        push_cand(v0.x, thr, i0 + 0, &s_cnt, s_pool);
        push_cand(v0.y, thr, i0 + 1, &s_cnt, s_pool);
        push_cand(v0.z, thr, i0 + 2, &s_cnt, s_pool);
        push_cand(v0.w, thr, i0 + 3, &s_cnt, s_pool);
        push_cand(v1.x, thr, i0 + 1024, &s_cnt, s_pool);
        push_cand(v1.y, thr, i0 + 1025, &s_cnt, s_pool);
        push_cand(v1.z, thr, i0 + 1026, &s_cnt, s_pool);
        push_cand(v1.w, thr, i0 + 1027, &s_cnt, s_pool);
        push_cand(v2.x, thr, i0 + 2048, &s_cnt, s_pool);
        push_cand(v2.y, thr, i0 + 2049, &s_cnt, s_pool);
        push_cand(v2.z, thr, i0 + 2050, &s_cnt, s_pool);
        push_cand(v2.w, thr, i0 + 2051, &s_cnt, s_pool);
        push_cand(v3.x, thr, i0 + 3072, &s_cnt, s_pool);
        push_cand(v3.y, thr, i0 + 3073, &s_cnt, s_pool);
        push_cand(v3.z, thr, i0 + 3074, &s_cnt, s_pool);
        push_cand(v3.w, thr, i0 + 3075, &s_cnt, s_pool);
    }
    __syncthreads();

    // Warp 0: select top-8 keys (value desc, index asc), write in index order.
    if (t < 32) {
        const int n = min(s_cnt, POOL_CAP);

        if (n <= 32) {
            // FAST PATH: one 32-lane bitonic sort of the zero-padded pool.
            u64 key = (t < n) ? s_pool[t] : 0ull;   // keys unique & nonzero
#pragma unroll
            for (int k = 2; k <= 32; k <<= 1) {
#pragma unroll
                for (int j = k >> 1; j > 0; j >>= 1) {
                    u64 o = __shfl_xor_sync(0xffffffffu, key, j);
                    bool take_max = (((lane & j) != 0) ^ ((lane & k) != 0));
                    key = take_max ? (key > o ? key : o) : (key < o ? key : o);
                }
            }
            // ascending: top-8 at lanes 24..31
            if (t >= 32 - KSEL) {
                unsigned fb = (unsigned)(key >> 12);
                float val = funflip(fb);
                int idx = 4095 - (int)(key & 0xfffu);
                int rank = 0;
#pragma unroll
                for (int j = 24; j < 32; j++) {
                    int oi = __shfl_sync(0xffffffffu, idx, j);
                    rank += (oi < idx);
                }
                out[row * KSEL + rank] = val;
            }
        } else {
            // SLOW PATH (rare): 8 rounds of warp-wide argmax.
            u64 mykey = 0ull;
#pragma unroll 1
            for (int k = 0; k < KSEL; k++) {
                u64 best = 0ull; int bpos = -1;
                for (int p = t; p < n; p += 32) {
                    u64 key = s_pool[p];
                    if (key > best) { best = key; bpos = p; }
                }
#pragma unroll
                for (int off = 16; off > 0; off >>= 1) {
                    u64 ob = __shfl_xor_sync(0xffffffffu, best, off);
                    int op = __shfl_xor_sync(0xffffffffu, bpos, off);
                    if (ob > best) { best = ob; bpos = op; }
                }
                if (t == k) mykey = best;
                if (t == 0) s_pool[bpos] = 0ull;
                __syncwarp();
            }
            if (t < KSEL) {
                unsigned fb = (unsigned)(mykey >> 12);
                float val = funflip(fb);
                int idx = 4095 - (int)(mykey & 0xfffu);
                int rank = 0;
#pragma unroll
                for (int j = 0; j < KSEL; j++) {
                    int oi = __shfl_sync(0xffu, idx, j);
                    rank += (oi < idx);
                }
                out[row * KSEL + rank] = val;
            }
        }
    }
}

extern "C" void kernel_launch(void* const* d_in, const int* in_sizes, int n_in,
                              void* d_out, int out_size) {
    const float* in = (const float*)d_in[0];
    float* out = (float*)d_out;
    int rows = in_sizes[0] / ROWLEN;   // B*C = 16384
    kmax_kernel<<<rows, NTHREADS>>>(in, out);
}

// round 7
// speedup vs baseline: 1.0457x; 1.0457x over previous
#include <cuda_runtime.h>
#include <cstdint>

#define NTHREADS 128
#define ROWLEN   4096
#define KSEL     8
#define POOL_CAP 256

typedef unsigned long long u64;

// Monotone bijection float -> uint32 (order preserving)
__device__ __forceinline__ unsigned fflip(float f) {
    unsigned u = __float_as_uint(f);
    return (u & 0x80000000u) ? ~u : (u | 0x80000000u);
}
__device__ __forceinline__ float funflip(unsigned u) {
    return __uint_as_float((u & 0x80000000u) ? (u ^ 0x80000000u) : ~u);
}

__device__ __forceinline__ void push_cand(float x, float thr, int idx,
                                          int* s_cnt, u64* s_pool) {
    if (x >= thr) {
        int pos = atomicAdd(s_cnt, 1);
        if (pos < POOL_CAP)
            s_pool[pos] = ((u64)fflip(x) << 12) | (unsigned)(4095 - idx);
    }
}

__global__ __launch_bounds__(NTHREADS) void kmax_kernel(const float* __restrict__ in,
                                                        float* __restrict__ out) {
    __shared__ unsigned s_m[4];       // per-warp m2 (flipped), 4 warps
    __shared__ int s_cnt;
    __shared__ u64 s_pool[POOL_CAP];

    const int t = threadIdx.x;
    const int lane = t & 31;
    const int wid = t >> 5;
    const size_t row = blockIdx.x;
    const float4* rp = reinterpret_cast<const float4*>(in + row * (size_t)ROWLEN);

    // Front-batched streaming loads: 8x LDG.128 per thread (MLP=8).
    float4 v[8];
#pragma unroll
    for (int i = 0; i < 8; i++)
        v[i] = __ldcs(rp + i * NTHREADS + t);

    if (t == 0) s_cnt = 0;

    // Per-thread max over its 32 elements (31 FMNMX).
    float gm = fmaxf(fmaxf(v[0].x, v[0].y), fmaxf(v[0].z, v[0].w));
#pragma unroll
    for (int i = 1; i < 8; i++)
        gm = fmaxf(gm, fmaxf(fmaxf(v[i].x, v[i].y), fmaxf(v[i].z, v[i].w)));
    const float gmax = gm;
    const unsigned gx = fflip(gmax);

    // Warp top-2 distinct thread-maxes via hardware REDUX.
    // m1-holder and m2-holder are different threads, so each warp certifies
    // >=2 distinct elements >= m2. (Ties zeroing all m1 holders only loosens
    // m2 -> still safe.)
    unsigned m1 = __reduce_max_sync(0xffffffffu, gx);
    unsigned m2 = __reduce_max_sync(0xffffffffu, (gx == m1) ? 0u : gx);
    if (lane == 0) s_m[wid] = m2;
    __syncthreads();

    // Threshold T = MIN over the 4 per-warp m2 values. Safety: each warp has
    // >=2 distinct elements >= its m2_w >= T -> >=8 elements >= T in the row;
    // any x < T is beaten by those 8 -> every true top-8 element passes.
    uint4 a = reinterpret_cast<const uint4*>(s_m)[0];
    unsigned tf = min(min(a.x, a.y), min(a.z, a.w));
    const float thr = funflip(tf);

    // Push candidate ELEMENTS (x >= thr). Typically ~8-15 per row; almost all
    // threads skip this branch (gmax < thr).
    if (gmax >= thr) {
#pragma unroll
        for (int c = 0; c < 8; c++) {
            int ib = c * 512 + 4 * t;
            push_cand(v[c].x, thr, ib + 0, &s_cnt, s_pool);
            push_cand(v[c].y, thr, ib + 1, &s_cnt, s_pool);
            push_cand(v[c].z, thr, ib + 2, &s_cnt, s_pool);
            push_cand(v[c].w, thr, ib + 3, &s_cnt, s_pool);
        }
    }
    __syncthreads();

    // Warp 0: select top-8 keys (value desc, index asc), write in index order.
    if (t < 32) {
        const int n = min(s_cnt, POOL_CAP);

        if (n <= 32) {
            // FAST PATH: one 32-lane bitonic sort of the zero-padded pool.
            u64 key = (t < n) ? s_pool[t] : 0ull;   // keys unique & nonzero
#pragma unroll
            for (int k = 2; k <= 32; k <<= 1) {
#pragma unroll
                for (int j = k >> 1; j > 0; j >>= 1) {
                    u64 o = __shfl_xor_sync(0xffffffffu, key, j);
                    bool take_max = (((lane & j) != 0) ^ ((lane & k) != 0));
                    key = take_max ? (key > o ? key : o) : (key < o ? key : o);
                }
            }
            // ascending: top-8 at lanes 24..31
            if (t >= 32 - KSEL) {
                unsigned fb = (unsigned)(key >> 12);
                float val = funflip(fb);
                int idx = 4095 - (int)(key & 0xfffu);
                int rank = 0;
#pragma unroll
                for (int j = 24; j < 32; j++) {
                    int oi = __shfl_sync(0xffffffffu, idx, j);
                    rank += (oi < idx);
                }
                out[row * KSEL + rank] = val;
            }
        } else {
            // SLOW PATH (rare): 8 rounds of warp-wide argmax.
            u64 mykey = 0ull;
#pragma unroll 1
            for (int k = 0; k < KSEL; k++) {
                u64 best = 0ull; int bpos = -1;
                for (int p = t; p < n; p += 32) {
                    u64 key = s_pool[p];
                    if (key > best) { best = key; bpos = p; }
                }
#pragma unroll
                for (int off = 16; off > 0; off >>= 1) {
                    u64 ob = __shfl_xor_sync(0xffffffffu, best, off);
                    int op = __shfl_xor_sync(0xffffffffu, bpos, off);
                    if (ob > best) { best = ob; bpos = op; }
                }
                if (t == k) mykey = best;
                if (t == 0) s_pool[bpos] = 0ull;
                __syncwarp();
            }
            if (t < KSEL) {
                unsigned fb = (unsigned)(mykey >> 12);
                float val = funflip(fb);
                int idx = 4095 - (int)(mykey & 0xfffu);
                int rank = 0;
#pragma unroll
                for (int j = 0; j < KSEL; j++) {
                    int oi = __shfl_sync(0xffu, idx, j);
                    rank += (oi < idx);
                }
                out[row * KSEL + rank] = val;
            }
        }
    }
}

extern "C" void kernel_launch(void* const* d_in, const int* in_sizes, int n_in,
                              void* d_out, int out_size) {
    const float* in = (const float*)d_in[0];
    float* out = (float*)d_out;
    int rows = in_sizes[0] / ROWLEN;   // B*C = 16384
    kmax_kernel<<<rows, NTHREADS>>>(in, out);
}